// round 16
// baseline (speedup 1.0000x reference)
#include <cuda_runtime.h>
#include <cuda_fp16.h>
#include <cstdint>

// ---------------------------------------------------------------------------
// LSTM cell w/ diagonal peepholes (round-15 champion + convert re-layout):
//   1) convert: lane-contiguous float4 loads (4 KB contiguous per instr per
//      block, MLP=4, __ldcs on sources) + prep tail (bias sums, peephole
//      diagonals into packed __device__ arrays).
//   2) GEMM: g_gates(fp16) = A @ W^T  (mma.sync m16n8k16 f32-acc,
//      3-stage cp.async pipeline, BK=64, ldmatrix.x4 both operands, 2 CTA/SM)
//      -- byte-identical to the measured-champion mainloop (~200us pipe floor).
//   3) coalesced LSTM epilogue, 2 batch rows per thread (byte-identical).
// tcgen05 unavailable (harness PTX targets plain sm_103, no 'a' features).
// ---------------------------------------------------------------------------

#define MB 4096
#define HD 1024
#define NG 4096
#define KT 2048

#define BM 128
#define BN 128
#define BKH 64              // K-halves per stage
#define NSTG 3
#define RSB 144             // smem row stride bytes (128B data + 16 pad)
#define TILE_BYTES (BM * RSB)          // 18432
#define STG_BYTES  (2 * TILE_BYTES)    // 36864 (A then B)
#define SMEM_BYTES (NSTG * STG_BYTES)  // 110592

__device__ __half g_A[(size_t)MB * KT];
__device__ __half g_W[(size_t)NG * KT];
__device__ __half g_gates[(size_t)MB * NG];     // fp16 pre-activation gates
__device__ float  g_BS[NG];                     // b_ih + b_hh (packed)
__device__ float  g_PI[HD];                     // diag(W_peephole_i)
__device__ float  g_PF[HD];                     // diag(W_peephole_f)

// ----------------------------- helpers ------------------------------------
__device__ __forceinline__ uint32_t smem_u32(const void* p) {
    uint32_t a;
    asm("{ .reg .u64 t; cvta.to.shared.u64 t, %1; cvt.u32.u64 %0, t; }"
        : "=r"(a) : "l"(p));
    return a;
}
__device__ __forceinline__ void cp16(uint32_t dst, const void* src) {
    asm volatile("cp.async.cg.shared.global [%0], [%1], 16;"
                 :: "r"(dst), "l"(src) : "memory");
}
#define CP_COMMIT() asm volatile("cp.async.commit_group;" ::: "memory")
#define CP_WAIT1()  asm volatile("cp.async.wait_group 1;"  ::: "memory")

#define LDSM_X4(r0, r1, r2, r3, addr) \
    asm volatile("ldmatrix.sync.aligned.m8n8.x4.shared.b16 {%0,%1,%2,%3}, [%4];" \
                 : "=r"(r0), "=r"(r1), "=r"(r2), "=r"(r3) : "r"(addr))

#define MMA16816(c, a, b) \
    asm volatile("mma.sync.aligned.m16n8k16.row.col.f32.f16.f16.f32 " \
                 "{%0,%1,%2,%3}, {%4,%5,%6,%7}, {%8,%9}, {%0,%1,%2,%3};" \
                 : "+f"((c)[0]), "+f"((c)[1]), "+f"((c)[2]), "+f"((c)[3]) \
                 : "r"((a)[0]), "r"((a)[1]), "r"((a)[2]), "r"((a)[3]), \
                   "r"((b)[0]), "r"((b)[1]))

__device__ __forceinline__ float sigmoidf_(float v) {
    return 1.0f / (1.0f + expf(-v));
}

// ----------------------------- convert + prep -----------------------------
// Data blocks (0..4095): block owns 1024 float4 of the concatenated fp32
// stream (A then W, each [rows x 2048] row-major). Load slot l: thread t
// reads float4 (l*256 + t) of the block's chunk -> 4 KB contiguous per
// instruction, 4 independent slots (MLP=4). Sources read with __ldcs.
// Prep blocks (4096..4119): bias sums + peephole diagonals.
__global__ __launch_bounds__(256)
void convert_f16(const float* __restrict__ x,  const float* __restrict__ hx,
                 const float* __restrict__ wih, const float* __restrict__ whh,
                 const float* __restrict__ b_ih, const float* __restrict__ b_hh,
                 const float* __restrict__ wpi, const float* __restrict__ wpf) {
    const size_t NAF4 = (size_t)MB * KT / 4;    // 2M float4 in A, 2M in W
    if (blockIdx.x < 4096) {
        const size_t base = (size_t)blockIdx.x * 1024;   // float4 index
        #pragma unroll
        for (int l = 0; l < 4; l++) {
            const size_t f = base + (size_t)l * 256 + threadIdx.x;
            const size_t j   = (f < NAF4) ? f : f - NAF4;  // float4 idx in matrix
            const size_t off = j * 4;                      // float offset
            const size_t row = off >> 11;                  // 2048 floats per row
            const size_t col = off & 2047;
            const float* src;
            __half* dst;
            if (f < NAF4) {
                src = (col < HD) ? (x + row * HD + col)
                                 : (hx + row * HD + (col - HD));
                dst = g_A + off;
            } else {
                src = (col < HD) ? (wih + row * HD + col)
                                 : (whh + row * HD + (col - HD));
                dst = g_W + off;
            }
            const float4 v = __ldcs((const float4*)src);
            __half2 h2[2];
            h2[0] = __floats2half2_rn(v.x, v.y);
            h2[1] = __floats2half2_rn(v.z, v.w);
            *(uint2*)dst = *(uint2*)h2;
        }
    } else {
        const size_t p = (size_t)(blockIdx.x - 4096) * 256 + threadIdx.x;
        if (p < NG) {
            g_BS[p] = b_ih[p] + b_hh[p];
        } else if (p < NG + HD) {
            const size_t h = p - NG;
            g_PI[h] = wpi[h * (HD + 1)];
        } else if (p < NG + 2 * HD) {
            const size_t h = p - NG - HD;
            g_PF[h] = wpf[h * (HD + 1)];
        }
    }
}

// ----------------------------- GEMM (champion, unchanged) ------------------
__global__ __launch_bounds__(256, 2)
void gates_gemm_f16() {
    extern __shared__ char smem[];
    const uint32_t sb = smem_u32(smem);

    const int tid  = threadIdx.x;
    const int lane = tid & 31;
    const int warp = tid >> 5;
    const int wm   = warp >> 2;          // 0..1 (64 rows each)
    const int wn   = warp & 3;           // 0..3 (32 cols each)
    const int bm   = blockIdx.y * BM;
    const int bn   = blockIdx.x * BN;

    const uint32_t aoff = (uint32_t)(lane & 15) * RSB + (uint32_t)(lane >> 4) * 16;
    const uint32_t boff = (uint32_t)(lane & 7) * RSB + (uint32_t)((lane >> 3) & 1) * 16
                        + (uint32_t)(lane >> 4) * (8 * RSB);

#define FILL(s_, kt_) do {                                                       \
        const uint32_t sa_ = sb + (uint32_t)(s_) * STG_BYTES;                    \
        const __half* ga_ = g_A + (size_t)(bm) * KT + (size_t)(kt_) * BKH;       \
        const __half* gw_ = g_W + (size_t)(bn) * KT + (size_t)(kt_) * BKH;       \
        _Pragma("unroll")                                                        \
        for (int i_ = 0; i_ < 4; i_++) {                                         \
            const int f_ = tid + i_ * 256;                                       \
            const int r_ = f_ >> 3, c_ = f_ & 7;                                 \
            cp16(sa_ + (uint32_t)r_ * RSB + (uint32_t)c_ * 16,                   \
                 ga_ + (size_t)r_ * KT + c_ * 8);                                \
            cp16(sa_ + TILE_BYTES + (uint32_t)r_ * RSB + (uint32_t)c_ * 16,      \
                 gw_ + (size_t)r_ * KT + c_ * 8);                                \
        }                                                                        \
    } while (0)

    FILL(0, 0); CP_COMMIT();
    FILL(1, 1); CP_COMMIT();

    float acc[4][4][4];
    #pragma unroll
    for (int i = 0; i < 4; i++)
        #pragma unroll
        for (int j = 0; j < 4; j++)
            #pragma unroll
            for (int e = 0; e < 4; e++) acc[i][j][e] = 0.0f;

    #pragma unroll 1
    for (int kt = 0; kt < KT / BKH; kt++) {       // 32 stages
        const int s = kt % 3;
        CP_WAIT1();
        __syncthreads();
        if (kt + 2 < KT / BKH) FILL((kt + 2) % 3, kt + 2);
        CP_COMMIT();

        const uint32_t sa = sb + (uint32_t)s * STG_BYTES;
        const uint32_t sw = sa + TILE_BYTES;
        #pragma unroll
        for (int ks = 0; ks < 4; ks++) {          // 16 halves each
            uint32_t a[4][4], b[4][2];
            #pragma unroll
            for (int mt = 0; mt < 4; mt++) {
                const uint32_t ad = sa + (uint32_t)(wm * 64 + mt * 16) * RSB
                                       + (uint32_t)ks * 32 + aoff;
                LDSM_X4(a[mt][0], a[mt][1], a[mt][2], a[mt][3], ad);
            }
            #pragma unroll
            for (int np = 0; np < 2; np++) {      // nt pairs {0,1},{2,3}
                const uint32_t bd = sw + (uint32_t)(wn * 32 + np * 16) * RSB
                                       + (uint32_t)ks * 32 + boff;
                LDSM_X4(b[np * 2][0], b[np * 2][1],
                        b[np * 2 + 1][0], b[np * 2 + 1][1], bd);
            }
            #pragma unroll
            for (int mt = 0; mt < 4; mt++)
                #pragma unroll
                for (int nt = 0; nt < 4; nt++)
                    MMA16816(acc[mt][nt], a[mt], b[nt]);
        }
    }
#undef FILL

    // store acc -> g_gates (fp16)
    const int g  = lane >> 2;
    const int tc = lane & 3;
    #pragma unroll
    for (int mt = 0; mt < 4; mt++) {
        #pragma unroll
        for (int nt = 0; nt < 4; nt++) {
            const int row = bm + wm * 64 + mt * 16 + g;
            const int col = bn + wn * 32 + nt * 8 + tc * 2;
            __half2* p0 = (__half2*)(g_gates + (size_t)row * NG + col);
            *p0 = __floats2half2_rn(acc[mt][nt][0], acc[mt][nt][1]);
            __half2* p1 = (__half2*)(g_gates + (size_t)(row + 8) * NG + col);
            *p1 = __floats2half2_rn(acc[mt][nt][2], acc[mt][nt][3]);
        }
    }
}

// ------------------- LSTM epilogue (2 batch rows per thread) ---------------
__global__ __launch_bounds__(256)
void lstm_epilogue(const float* __restrict__ cx, float* __restrict__ out) {
    const int idx4 = (blockIdx.x * 256 + threadIdx.x) * 4;  // over MB/2 x HD
    const int b = idx4 >> 10;
    const int h = idx4 & (HD - 1);

    const float4 bs0 = *(const float4*)(g_BS + h);
    const float4 bs1 = *(const float4*)(g_BS + HD + h);
    const float4 bs2 = *(const float4*)(g_BS + 2 * HD + h);
    const float4 bs3 = *(const float4*)(g_BS + 3 * HD + h);
    const float4 pi4 = *(const float4*)(g_PI + h);
    const float4 pf4 = *(const float4*)(g_PF + h);
    const float bsi[4] = {bs0.x, bs0.y, bs0.z, bs0.w};
    const float bsf[4] = {bs1.x, bs1.y, bs1.z, bs1.w};
    const float bsg[4] = {bs2.x, bs2.y, bs2.z, bs2.w};
    const float bso[4] = {bs3.x, bs3.y, bs3.z, bs3.w};
    const float piv[4] = {pi4.x, pi4.y, pi4.z, pi4.w};
    const float pfv[4] = {pf4.x, pf4.y, pf4.z, pf4.w};

    #pragma unroll
    for (int rr = 0; rr < 2; rr++) {
        const int bb = b + rr * (MB / 2);
        const size_t base = (size_t)bb * HD + h;

        const __half* gr = g_gates + (size_t)bb * NG;
        float ig[4], fg[4], gg[4], og[4];
        #pragma unroll
        for (int G = 0; G < 4; G++) {
            const uint2 raw = *(const uint2*)(gr + G * HD + h);
            const float2 lo = __half22float2(*(const __half2*)&raw.x);
            const float2 hi = __half22float2(*(const __half2*)&raw.y);
            float* dst = (G == 0) ? ig : (G == 1) ? fg : (G == 2) ? gg : og;
            dst[0] = lo.x; dst[1] = lo.y; dst[2] = hi.x; dst[3] = hi.y;
        }
        const float4 c4 = *(const float4*)(cx + base);
        const float cv[4] = {c4.x, c4.y, c4.z, c4.w};

        float hy[4], cy[4];
        #pragma unroll
        for (int e = 0; e < 4; e++) {
            const float c  = cv[e];
            const float i_s = sigmoidf_(ig[e] + bsi[e] + c * piv[e]);
            const float f_s = sigmoidf_(fg[e] + bsf[e] + c * pfv[e]);
            const float g_t = tanhf(gg[e] + bsg[e]);
            const float cyv = f_s * c + i_s * g_t;
            const float o_s = sigmoidf_(og[e] + bso[e] + cyv * pfv[e]); // ref reuses W_f
            hy[e] = o_s * tanhf(cyv);
            cy[e] = cyv;
        }
        *(float4*)(out + base) = make_float4(hy[0], hy[1], hy[2], hy[3]);
        *(float4*)(out + (size_t)MB * HD + base) =
            make_float4(cy[0], cy[1], cy[2], cy[3]);
    }
}

// ---------------------------------------------------------------------------
extern "C" void kernel_launch(void* const* d_in, const int* in_sizes, int n_in,
                              void* d_out, int out_size) {
    const float* x    = (const float*)d_in[0];
    const float* hx   = (const float*)d_in[1];
    const float* cx   = (const float*)d_in[2];
    const float* w_ih = (const float*)d_in[3];
    const float* w_hh = (const float*)d_in[4];
    const float* b_ih = (const float*)d_in[5];
    const float* b_hh = (const float*)d_in[6];
    const float* wpi  = (const float*)d_in[7];
    const float* wpf  = (const float*)d_in[8];
    // d_in[9] (W_peephole_o) unused: reference reuses W_peephole_f.
    float* out = (float*)d_out;

    // 4096 data blocks + 24 prep blocks (6144 prep elements)
    convert_f16<<<4120, 256>>>(x, hx, w_ih, w_hh, b_ih, b_hh, wpi, wpf);

    static int smem_set = 0;
    if (!smem_set) {
        cudaFuncSetAttribute(gates_gemm_f16,
                             cudaFuncAttributeMaxDynamicSharedMemorySize,
                             SMEM_BYTES);
        smem_set = 1;
    }
    dim3 grid(NG / BN, MB / BM);   // 32 x 32
    gates_gemm_f16<<<grid, 256, SMEM_BYTES>>>();

    // (MB/2 * HD) / 4 elems per thread / 256 threads = 2048 blocks
    lstm_epilogue<<<(MB / 2 * HD) / 1024, 256>>>(cx, out);
}

// round 17
// speedup vs baseline: 1.0064x; 1.0064x over previous
#include <cuda_runtime.h>
#include <cuda_fp16.h>
#include <cstdint>

// ---------------------------------------------------------------------------
// LSTM cell w/ diagonal peepholes — FINAL (round-15 champion, 223.7us):
//   1) convert (16 elem/thread, per-thread 64B chunks) + prep tail
//      (bias sums + peephole diagonals into packed __device__ arrays).
//      Measured at the HBM mixed-stream floor (~16us).
//   2) GEMM: g_gates(fp16) = A @ W^T  (mma.sync m16n8k16 f32-acc,
//      3-stage cp.async pipeline, BK=64, ldmatrix.x4 both operands, 2 CTA/SM).
//      Measured at the legacy-HMMA rt16 issue floor (~200us).
//   3) coalesced LSTM epilogue, 2 batch rows/thread (~7us, traffic floor).
// tcgen05 unavailable (harness PTX targets plain sm_103, no 'a' features).
// ---------------------------------------------------------------------------

#define MB 4096
#define HD 1024
#define NG 4096
#define KT 2048

#define BM 128
#define BN 128
#define BKH 64              // K-halves per stage
#define NSTG 3
#define RSB 144             // smem row stride bytes (128B data + 16 pad)
#define TILE_BYTES (BM * RSB)          // 18432
#define STG_BYTES  (2 * TILE_BYTES)    // 36864 (A then B)
#define SMEM_BYTES (NSTG * STG_BYTES)  // 110592

__device__ __half g_A[(size_t)MB * KT];
__device__ __half g_W[(size_t)NG * KT];
__device__ __half g_gates[(size_t)MB * NG];     // fp16 pre-activation gates
__device__ float  g_BS[NG];                     // b_ih + b_hh (packed)
__device__ float  g_PI[HD];                     // diag(W_peephole_i)
__device__ float  g_PF[HD];                     // diag(W_peephole_f)

// ----------------------------- helpers ------------------------------------
__device__ __forceinline__ uint32_t smem_u32(const void* p) {
    uint32_t a;
    asm("{ .reg .u64 t; cvta.to.shared.u64 t, %1; cvt.u32.u64 %0, t; }"
        : "=r"(a) : "l"(p));
    return a;
}
__device__ __forceinline__ void cp16(uint32_t dst, const void* src) {
    asm volatile("cp.async.cg.shared.global [%0], [%1], 16;"
                 :: "r"(dst), "l"(src) : "memory");
}
#define CP_COMMIT() asm volatile("cp.async.commit_group;" ::: "memory")
#define CP_WAIT1()  asm volatile("cp.async.wait_group 1;"  ::: "memory")

#define LDSM_X4(r0, r1, r2, r3, addr) \
    asm volatile("ldmatrix.sync.aligned.m8n8.x4.shared.b16 {%0,%1,%2,%3}, [%4];" \
                 : "=r"(r0), "=r"(r1), "=r"(r2), "=r"(r3) : "r"(addr))

#define MMA16816(c, a, b) \
    asm volatile("mma.sync.aligned.m16n8k16.row.col.f32.f16.f16.f32 " \
                 "{%0,%1,%2,%3}, {%4,%5,%6,%7}, {%8,%9}, {%0,%1,%2,%3};" \
                 : "+f"((c)[0]), "+f"((c)[1]), "+f"((c)[2]), "+f"((c)[3]) \
                 : "r"((a)[0]), "r"((a)[1]), "r"((a)[2]), "r"((a)[3]), \
                   "r"((b)[0]), "r"((b)[1]))

__device__ __forceinline__ float sigmoidf_(float v) {
    return 1.0f / (1.0f + expf(-v));
}

// ----------------------------- convert + prep -----------------------------
// Data blocks (0..4095): each thread converts 16 consecutive fp32 to fp16.
// Prep blocks (4096..4119): extract bias sums + peephole diagonals.
__global__ __launch_bounds__(256)
void convert_f16(const float* __restrict__ x,  const float* __restrict__ hx,
                 const float* __restrict__ wih, const float* __restrict__ whh,
                 const float* __restrict__ b_ih, const float* __restrict__ b_hh,
                 const float* __restrict__ wpi, const float* __restrict__ wpf) {
    const size_t NA16 = (size_t)MB * KT / 16;   // 512K picks for A, 512K for W
    const size_t id = (size_t)blockIdx.x * blockDim.x + threadIdx.x;
    if (id < 2 * NA16) {
        const size_t j   = (id < NA16) ? id : id - NA16;
        const size_t row = j >> 7;
        const size_t k16 = (j & 127) * 16;
        const float* src;
        __half* dst;
        if (id < NA16) {
            src = (k16 < HD) ? (x + row * HD + k16) : (hx + row * HD + (k16 - HD));
            dst = g_A + j * 16;
        } else {
            src = (k16 < HD) ? (wih + row * HD + k16) : (whh + row * HD + (k16 - HD));
            dst = g_W + j * 16;
        }
        float4 v0 = *(const float4*)(src);
        float4 v1 = *(const float4*)(src + 4);
        float4 v2 = *(const float4*)(src + 8);
        float4 v3 = *(const float4*)(src + 12);
        __half2 h_[8];
        h_[0] = __floats2half2_rn(v0.x, v0.y); h_[1] = __floats2half2_rn(v0.z, v0.w);
        h_[2] = __floats2half2_rn(v1.x, v1.y); h_[3] = __floats2half2_rn(v1.z, v1.w);
        h_[4] = __floats2half2_rn(v2.x, v2.y); h_[5] = __floats2half2_rn(v2.z, v2.w);
        h_[6] = __floats2half2_rn(v3.x, v3.y); h_[7] = __floats2half2_rn(v3.z, v3.w);
        *(uint4*)(dst)     = *(uint4*)&h_[0];
        *(uint4*)(dst + 8) = *(uint4*)&h_[4];
    } else {
        const size_t p = id - 2 * NA16;          // 0 .. 6143
        if (p < NG) {
            g_BS[p] = b_ih[p] + b_hh[p];
        } else if (p < NG + HD) {
            const size_t h = p - NG;
            g_PI[h] = wpi[h * (HD + 1)];
        } else if (p < NG + 2 * HD) {
            const size_t h = p - NG - HD;
            g_PF[h] = wpf[h * (HD + 1)];
        }
    }
}

// ----------------------------- GEMM (champion, unchanged) ------------------
__global__ __launch_bounds__(256, 2)
void gates_gemm_f16() {
    extern __shared__ char smem[];
    const uint32_t sb = smem_u32(smem);

    const int tid  = threadIdx.x;
    const int lane = tid & 31;
    const int warp = tid >> 5;
    const int wm   = warp >> 2;          // 0..1 (64 rows each)
    const int wn   = warp & 3;           // 0..3 (32 cols each)
    const int bm   = blockIdx.y * BM;
    const int bn   = blockIdx.x * BN;

    const uint32_t aoff = (uint32_t)(lane & 15) * RSB + (uint32_t)(lane >> 4) * 16;
    const uint32_t boff = (uint32_t)(lane & 7) * RSB + (uint32_t)((lane >> 3) & 1) * 16
                        + (uint32_t)(lane >> 4) * (8 * RSB);

#define FILL(s_, kt_) do {                                                       \
        const uint32_t sa_ = sb + (uint32_t)(s_) * STG_BYTES;                    \
        const __half* ga_ = g_A + (size_t)(bm) * KT + (size_t)(kt_) * BKH;       \
        const __half* gw_ = g_W + (size_t)(bn) * KT + (size_t)(kt_) * BKH;       \
        _Pragma("unroll")                                                        \
        for (int i_ = 0; i_ < 4; i_++) {                                         \
            const int f_ = tid + i_ * 256;                                       \
            const int r_ = f_ >> 3, c_ = f_ & 7;                                 \
            cp16(sa_ + (uint32_t)r_ * RSB + (uint32_t)c_ * 16,                   \
                 ga_ + (size_t)r_ * KT + c_ * 8);                                \
            cp16(sa_ + TILE_BYTES + (uint32_t)r_ * RSB + (uint32_t)c_ * 16,      \
                 gw_ + (size_t)r_ * KT + c_ * 8);                                \
        }                                                                        \
    } while (0)

    FILL(0, 0); CP_COMMIT();
    FILL(1, 1); CP_COMMIT();

    float acc[4][4][4];
    #pragma unroll
    for (int i = 0; i < 4; i++)
        #pragma unroll
        for (int j = 0; j < 4; j++)
            #pragma unroll
            for (int e = 0; e < 4; e++) acc[i][j][e] = 0.0f;

    #pragma unroll 1
    for (int kt = 0; kt < KT / BKH; kt++) {       // 32 stages
        const int s = kt % 3;
        CP_WAIT1();
        __syncthreads();
        if (kt + 2 < KT / BKH) FILL((kt + 2) % 3, kt + 2);
        CP_COMMIT();

        const uint32_t sa = sb + (uint32_t)s * STG_BYTES;
        const uint32_t sw = sa + TILE_BYTES;
        #pragma unroll
        for (int ks = 0; ks < 4; ks++) {          // 16 halves each
            uint32_t a[4][4], b[4][2];
            #pragma unroll
            for (int mt = 0; mt < 4; mt++) {
                const uint32_t ad = sa + (uint32_t)(wm * 64 + mt * 16) * RSB
                                       + (uint32_t)ks * 32 + aoff;
                LDSM_X4(a[mt][0], a[mt][1], a[mt][2], a[mt][3], ad);
            }
            #pragma unroll
            for (int np = 0; np < 2; np++) {      // nt pairs {0,1},{2,3}
                const uint32_t bd = sw + (uint32_t)(wn * 32 + np * 16) * RSB
                                       + (uint32_t)ks * 32 + boff;
                LDSM_X4(b[np * 2][0], b[np * 2][1],
                        b[np * 2 + 1][0], b[np * 2 + 1][1], bd);
            }
            #pragma unroll
            for (int mt = 0; mt < 4; mt++)
                #pragma unroll
                for (int nt = 0; nt < 4; nt++)
                    MMA16816(acc[mt][nt], a[mt], b[nt]);
        }
    }
#undef FILL

    // store acc -> g_gates (fp16)
    const int g  = lane >> 2;
    const int tc = lane & 3;
    #pragma unroll
    for (int mt = 0; mt < 4; mt++) {
        #pragma unroll
        for (int nt = 0; nt < 4; nt++) {
            const int row = bm + wm * 64 + mt * 16 + g;
            const int col = bn + wn * 32 + nt * 8 + tc * 2;
            __half2* p0 = (__half2*)(g_gates + (size_t)row * NG + col);
            *p0 = __floats2half2_rn(acc[mt][nt][0], acc[mt][nt][1]);
            __half2* p1 = (__half2*)(g_gates + (size_t)(row + 8) * NG + col);
            *p1 = __floats2half2_rn(acc[mt][nt][2], acc[mt][nt][3]);
        }
    }
}

// ------------------- LSTM epilogue (2 batch rows per thread) ---------------
__global__ __launch_bounds__(256)
void lstm_epilogue(const float* __restrict__ cx, float* __restrict__ out) {
    // thread covers (b, h..h+3) and (b + MB/2, h..h+3): same h-constants.
    const int idx4 = (blockIdx.x * 256 + threadIdx.x) * 4;  // over MB/2 x HD
    const int b = idx4 >> 10;
    const int h = idx4 & (HD - 1);

    // h-constants loaded once, reused for both rows
    const float4 bs0 = *(const float4*)(g_BS + h);
    const float4 bs1 = *(const float4*)(g_BS + HD + h);
    const float4 bs2 = *(const float4*)(g_BS + 2 * HD + h);
    const float4 bs3 = *(const float4*)(g_BS + 3 * HD + h);
    const float4 pi4 = *(const float4*)(g_PI + h);
    const float4 pf4 = *(const float4*)(g_PF + h);
    const float bsi[4] = {bs0.x, bs0.y, bs0.z, bs0.w};
    const float bsf[4] = {bs1.x, bs1.y, bs1.z, bs1.w};
    const float bsg[4] = {bs2.x, bs2.y, bs2.z, bs2.w};
    const float bso[4] = {bs3.x, bs3.y, bs3.z, bs3.w};
    const float piv[4] = {pi4.x, pi4.y, pi4.z, pi4.w};
    const float pfv[4] = {pf4.x, pf4.y, pf4.z, pf4.w};

    #pragma unroll
    for (int rr = 0; rr < 2; rr++) {
        const int bb = b + rr * (MB / 2);
        const size_t base = (size_t)bb * HD + h;

        const __half* gr = g_gates + (size_t)bb * NG;
        float ig[4], fg[4], gg[4], og[4];
        #pragma unroll
        for (int G = 0; G < 4; G++) {
            const uint2 raw = *(const uint2*)(gr + G * HD + h);
            const float2 lo = __half22float2(*(const __half2*)&raw.x);
            const float2 hi = __half22float2(*(const __half2*)&raw.y);
            float* dst = (G == 0) ? ig : (G == 1) ? fg : (G == 2) ? gg : og;
            dst[0] = lo.x; dst[1] = lo.y; dst[2] = hi.x; dst[3] = hi.y;
        }
        const float4 c4 = *(const float4*)(cx + base);
        const float cv[4] = {c4.x, c4.y, c4.z, c4.w};

        float hy[4], cy[4];
        #pragma unroll
        for (int e = 0; e < 4; e++) {
            const float c  = cv[e];
            const float i_s = sigmoidf_(ig[e] + bsi[e] + c * piv[e]);
            const float f_s = sigmoidf_(fg[e] + bsf[e] + c * pfv[e]);
            const float g_t = tanhf(gg[e] + bsg[e]);
            const float cyv = f_s * c + i_s * g_t;
            const float o_s = sigmoidf_(og[e] + bso[e] + cyv * pfv[e]); // ref reuses W_f
            hy[e] = o_s * tanhf(cyv);
            cy[e] = cyv;
        }
        *(float4*)(out + base) = make_float4(hy[0], hy[1], hy[2], hy[3]);
        *(float4*)(out + (size_t)MB * HD + base) =
            make_float4(cy[0], cy[1], cy[2], cy[3]);
    }
}

// ---------------------------------------------------------------------------
extern "C" void kernel_launch(void* const* d_in, const int* in_sizes, int n_in,
                              void* d_out, int out_size) {
    const float* x    = (const float*)d_in[0];
    const float* hx   = (const float*)d_in[1];
    const float* cx   = (const float*)d_in[2];
    const float* w_ih = (const float*)d_in[3];
    const float* w_hh = (const float*)d_in[4];
    const float* b_ih = (const float*)d_in[5];
    const float* b_hh = (const float*)d_in[6];
    const float* wpi  = (const float*)d_in[7];
    const float* wpf  = (const float*)d_in[8];
    // d_in[9] (W_peephole_o) unused: reference reuses W_peephole_f.
    float* out = (float*)d_out;

    // 4096 data blocks + 24 prep blocks (6144 prep elements)
    convert_f16<<<4120, 256>>>(x, hx, w_ih, w_hh, b_ih, b_hh, wpi, wpf);

    static int smem_set = 0;
    if (!smem_set) {
        cudaFuncSetAttribute(gates_gemm_f16,
                             cudaFuncAttributeMaxDynamicSharedMemorySize,
                             SMEM_BYTES);
        smem_set = 1;
    }
    dim3 grid(NG / BN, MB / BM);   // 32 x 32
    gates_gemm_f16<<<grid, 256, SMEM_BYTES>>>();

    // (MB/2 * HD) / 4 elems per thread / 256 threads = 2048 blocks
    lstm_epilogue<<<(MB / 2 * HD) / 1024, 256>>>(cx, out);
}